// round 16
// baseline (speedup 1.0000x reference)
#include <cuda_runtime.h>
#include <cuda_bf16.h>
#include <math.h>

#define BB 4096
#define LL 200
#define FF 8
#define DD 64
#define KK 15
#define NT 192              // 192-thread CTAs -> 10 CTAs/SM -> 2.77 waves (vs 3.46)
// dynamic smem: per-row partials [200][8] float2 (each = dot/ssq over 8 floats)
#define SMEM_BYTES (LL * 8 * 8)   // 12800 B

typedef unsigned long long u64;

#define MUL2(d, a, b)    asm("mul.rn.f32x2 %0, %1, %2;"     : "=l"(d) : "l"(a), "l"(b))
#define FMA2(d, a, b, c) asm("fma.rn.f32x2 %0, %1, %2, %3;" : "=l"(d) : "l"(a), "l"(b), "l"(c))

union F4U2 { float4 f4; u64 u2[2]; };

__device__ __forceinline__ float2 unpack2(u64 v) {
    float2 r;
    asm("mov.b64 {%0, %1}, %2;" : "=f"(r.x), "=f"(r.y) : "l"(v));
    return r;
}

__device__ __forceinline__ u64 mkKey(float s, int l) {
    return ((u64)__float_as_uint(s) << 32) | (unsigned)(LL - 1 - l);
}

__global__ void __launch_bounds__(NT, 10) search_predict_kernel(
    const int* __restrict__ x,        // [B, L, F] int32
    const int* __restrict__ self_loc, // [B] int32
    const float* __restrict__ E,      // [NFEAT+1, D] float32
    float* __restrict__ out)          // [B*16*8] x_out-as-float, then [B*15] sim_topk
{
    extern __shared__ __align__(16) float partials[];   // [200][8] float2, rot-swizzled

    __shared__ __align__(16) float4 selfv[16];          // self embedding row
    __shared__ int catS[LL];
    __shared__ __align__(16) float simF[224];           // raw float sims (no NaNs)
    __shared__ unsigned long long selKey[KK];           // {float bits, 199 - l}
    __shared__ int sortedL[KK + 1];
    __shared__ float invns;

    const int b    = blockIdx.x;
    const int tid  = threadIdx.x;
    const int warp = tid >> 5;

    const int* xb = x + (size_t)b * (LL * FF);
    const int sl = __ldg(self_loc + b);

    // catS rows <= sl (threads cover 0..191; threads 0..7 also 192..199)
    if (tid <= sl) catS[tid] = __ldg(xb + tid * FF + 5);
    if (tid < 8 && tid + NT <= sl) catS[tid + NT] = __ldg(xb + (tid + NT) * FF + 5);
    // warp 5 loads self row + precomputes inv-norm
    if (warp == 5) {
        const int hl = tid & 15;
        if ((tid & 31) < 16) {
            const int cs = __ldg(xb + sl * FF + 5);
            selfv[hl] = __ldg(reinterpret_cast<const float4*>(E + (size_t)cs * DD) + hl);
        }
        __syncwarp();
        const float4 s = selfv[hl];                       // lanes 16-31 mirror 0-15
        float q = s.x * s.x + s.y * s.y + s.z * s.z + s.w * s.w;
        q += __shfl_xor_sync(0xffffffffu, q, 8);
        q += __shfl_xor_sync(0xffffffffu, q, 4);
        q += __shfl_xor_sync(0xffffffffu, q, 2);
        q += __shfl_xor_sync(0xffffffffu, q, 1);
        if (tid == 160) invns = rsqrtf(q + 1e-8f);
    }
    __syncthreads();

    // ---- Phase A: fused gather + partials (packed f32x2 math), rows l <= sl ----
    {
        const int rg = tid >> 3;          // row 0..23 within 24-row tile
        const int j8 = tid & 7;           // owns float4 slices j8 and j8+8
        F4U2 sa, sb;
        sa.f4 = selfv[j8];
        sb.f4 = selfv[j8 + 8];
        const u64 sa0 = sa.u2[0], sa1 = sa.u2[1];
        const u64 sb0 = sb.u2[0], sb1 = sb.u2[1];
        #pragma unroll
        for (int it = 0; it < 9; ++it) {                  // rows 0..215
            const int l = it * 24 + rg;
            if (l <= sl) {                // warp-uniform except boundary warp
                const int c = catS[l];
                const float4* rp = reinterpret_cast<const float4*>(E + (size_t)c * DD);
                F4U2 va, vb;
                va.f4 = __ldg(rp + j8);
                vb.f4 = __ldg(rp + j8 + 8);
                u64 d2, q2;
                MUL2(d2, va.u2[0], sa0);
                FMA2(d2, va.u2[1], sa1, d2);
                FMA2(d2, vb.u2[0], sb0, d2);
                FMA2(d2, vb.u2[1], sb1, d2);
                MUL2(q2, va.u2[0], va.u2[0]);
                FMA2(q2, va.u2[1], va.u2[1], q2);
                FMA2(q2, vb.u2[0], vb.u2[0], q2);
                FMA2(q2, vb.u2[1], vb.u2[1], q2);
                const float2 dd = unpack2(d2);
                const float2 qq = unpack2(q2);
                // rotation swizzle: partial j8 of row l -> 16B chunk ((j8>>1)+(l>>1))&3
                const int byteoff = l * 64 + ((((j8 >> 1) + (l >> 1)) & 3) << 4)
                                  + ((j8 & 1) << 3);
                *reinterpret_cast<float2*>(reinterpret_cast<char*>(partials) + byteoff)
                    = make_float2(dd.x + dd.y, qq.x + qq.y);
            }
        }
    }
    __syncthreads();

    // ---- Phase B: per-row reduction. row1 = tid; row2 = tid+192 (tid<32) ----
    float sim1 = -2.0f;
    if (tid < sl) {
        float dot = 0.f, ssq = 0.f;
        const char* base = reinterpret_cast<const char*>(partials) + tid * 64;
        const int rot = (tid >> 1) & 3;
        #pragma unroll
        for (int k = 0; k < 4; ++k) {     // logical chunk order fixed (bit-exact dups)
            const float4 c = *reinterpret_cast<const float4*>(base + (((k + rot) & 3) << 4));
            dot += c.x + c.z;
            ssq += c.y + c.w;
        }
        sim1 = dot * rsqrtf(ssq + 1e-8f) * invns;
    }
    simF[tid] = sim1;
    if (tid < 32) {                        // rows 192..223 (pads / rare real rows)
        const int r2 = tid + NT;
        float sim2 = -2.0f;
        if (r2 < sl) {                     // only when sl >= 193 (rare)
            float dot = 0.f, ssq = 0.f;
            const char* base = reinterpret_cast<const char*>(partials) + r2 * 64;
            const int rot = (r2 >> 1) & 3;
            #pragma unroll
            for (int k = 0; k < 4; ++k) {
                const float4 c = *reinterpret_cast<const float4*>(base + (((k + rot) & 3) << 4));
                dot += c.x + c.z;
                ssq += c.y + c.w;
            }
            sim2 = dot * rsqrtf(ssq + 1e-8f) * invns;
        }
        simF[r2] = sim2;
    }
    __syncthreads();

    // ---- rank-select among first sl sims (float fast path) ----
    int rank1 = LL, rank2 = LL;
    const float4* p = reinterpret_cast<const float4*>(simF);
    const int nj = (sl + 3) >> 2;
    if (tid < 32 && tid + NT < sl) {       // rare second row first (regs die early)
        const float s2 = simF[tid + NT];
        int r = 0;
        for (int j = 0; j < nj; ++j) {
            const float4 k = p[j];
            r += (k.x > s2); r += (k.y > s2); r += (k.z > s2); r += (k.w > s2);
        }
        rank2 = r;
        if (r < KK) selKey[r] = mkKey(s2, tid + NT);
    }
    if (tid < sl) {
        int r = 0;
        for (int j = 0; j < nj; ++j) {      // broadcast LDS.128
            const float4 k = p[j];
            r += (k.x > sim1); r += (k.y > sim1); r += (k.z > sim1); r += (k.w > sim1);
        }
        rank1 = r;
        if (r < KK) selKey[r] = mkKey(sim1, tid);
    }
    __syncthreads();                        // publish selKey

    // tie inside top-K -> shared slot -> loser detects; rare exact recount
    int pred = (rank1 < KK) && (selKey[rank1] != mkKey(sim1, tid));
    if (rank2 < KK) pred |= (selKey[rank2] != mkKey(simF[tid + NT], tid + NT));
    if (__syncthreads_or(pred)) {
        if (tid < sl) {
            int r2 = 0;
            for (int j = 0; j < sl; ++j) {
                const float fj = simF[j];
                r2 += (fj > sim1) || (fj == sim1 && j < tid);
            }
            if (r2 < KK) selKey[r2] = mkKey(sim1, tid);
        }
        if (tid < 32 && tid + NT < sl) {
            const float s2 = simF[tid + NT];
            int r2 = 0;
            for (int j = 0; j < sl; ++j) {
                const float fj = simF[j];
                r2 += (fj > s2) || (fj == s2 && j < tid + NT);
            }
            if (r2 < KK) selKey[r2] = mkKey(s2, tid + NT);
        }
        __syncthreads();
    }

    // ---- warp 0: sort 15 by ascending index, emit sim_topk + x_out ----
    if (warp == 0) {
        if (tid < KK) {
            const unsigned long long mk = selKey[tid];
            const unsigned myLow = (unsigned)mk;    // 199 - l (larger = smaller l)
            int pos = 0;
            #pragma unroll
            for (int j = 0; j < KK; ++j) pos += ((unsigned)selKey[j] > myLow);
            sortedL[pos] = LL - 1 - (int)myLow;
            out[(size_t)BB * ((KK + 1) * FF) + (size_t)b * KK + pos]
                = __uint_as_float((unsigned)(mk >> 32));
        }
        if (tid == KK) sortedL[KK] = sl;
        __syncwarp();
        // x_out: 16 rows x 8 feats as float, 2 lanes per row (int4 -> float4)
        const int r    = tid >> 1;
        const int half = tid & 1;
        const int l = sortedL[r];
        const int4 v = __ldg(reinterpret_cast<const int4*>(xb + l * FF) + half);
        const float4 f = make_float4((float)v.x, (float)v.y, (float)v.z, (float)v.w);
        reinterpret_cast<float4*>(out + (size_t)b * ((KK + 1) * FF))[tid] = f;
    }
}

extern "C" void kernel_launch(void* const* d_in, const int* in_sizes, int n_in,
                              void* d_out, int out_size) {
    const int*   x  = (const int*)d_in[0];   // x: [4096, 200, 8] int32
    const int*   sl = (const int*)d_in[1];   // self_loc: [4096] int32
    const float* E  = (const float*)d_in[2]; // E: [100001, 64] float32
    float* out = (float*)d_out;

    search_predict_kernel<<<BB, NT, SMEM_BYTES>>>(x, sl, E, out);
}